// round 7
// baseline (speedup 1.0000x reference)
#include <cuda_runtime.h>

#define NSTATE 64

__global__ __launch_bounds__(256) void s4_cauchy_kernel(
    const float* __restrict__ Lr, const float* __restrict__ Li,
    const float* __restrict__ Pr, const float* __restrict__ Pi,
    const float* __restrict__ Qr, const float* __restrict__ Qi,
    const float* __restrict__ Br, const float* __restrict__ Bi,
    const float* __restrict__ Cr, const float* __restrict__ Ci,
    const float* __restrict__ step_ptr,
    float* __restrict__ out, int L)
{
    // Per-n data, broadcast-read by every thread in the block.
    __shared__ float4 sA[NSTATE];  // {lambda_re, lambda_im, v00_re, v00_im}
    __shared__ float4 sB[NSTATE];  // {v01_re, v01_im, v10_re, v10_im}
    __shared__ float2 sC[NSTATE];  // {v11_re, v11_im}

    const int t = threadIdx.x;
    if (t < NSTATE) {
        float cr = Cr[t], ci = Ci[t];
        float qr = Qr[t], qi = Qi[t];
        float br = Br[t], bi = Bi[t];
        float pr = Pr[t], pi = Pi[t];
        // a0 = conj(C), a1 = conj(Q); b0 = B, b1 = P
        // v00 = conj(C)*B, v01 = conj(C)*P, v10 = conj(Q)*B, v11 = conj(Q)*P
        float v00r = cr * br + ci * bi, v00i = cr * bi - ci * br;
        float v01r = cr * pr + ci * pi, v01i = cr * pi - ci * pr;
        float v10r = qr * br + qi * bi, v10i = qr * bi - qi * br;
        float v11r = qr * pr + qi * pi, v11i = qr * pi - qi * pr;
        sA[t] = make_float4(Lr[t], Li[t], v00r, v00i);
        sB[t] = make_float4(v01r, v01i, v10r, v10i);
        sC[t] = make_float2(v11r, v11i);
    }
    __syncthreads();

    const int k = blockIdx.x * blockDim.x + threadIdx.x;
    if (k >= L) return;

    const float two_over_step = 2.0f / step_ptr[0];

    // Omega = exp(-2*pi*i * k / L)
    const float TWO_PI = 6.283185307179586476925f;
    float ang = -TWO_PI * ((float)k / (float)L);
    float sw, cw;
    sincosf(ang, &sw, &cw);

    float opr = 1.0f + cw, opi = sw;     // 1 + Omega
    float omr = 1.0f - cw, omi = -sw;    // 1 - Omega
    float invd = __fdividef(1.0f, opr * opr + opi * opi);

    // g = (2/step) * (1 - Omega)/(1 + Omega)   (= i*(2/step)*tan(theta/2))
    float gr = (omr * opr + omi * opi) * invd * two_over_step;
    float gi = (omi * opr - omr * opi) * invd * two_over_step;
    // c = 2 / (1 + Omega)                      (= 1 + i*tan(theta/2))
    float c_r =  2.0f * opr * invd;
    float c_i = -2.0f * opi * invd;

    float k00r = 0.f, k00i = 0.f;
    float k01r = 0.f, k01i = 0.f;
    float k10r = 0.f, k10i = 0.f;
    float k11r = 0.f, k11i = 0.f;

#pragma unroll 16
    for (int n = 0; n < NSTATE; n++) {
        float4 a = sA[n];
        float4 b = sB[n];
        float2 cc = sC[n];
        // denom = g - lambda_n; inv = conj(denom)/|denom|^2
        float dr = gr - a.x;
        float di = gi - a.y;
        float m  = dr * dr + di * di;
        float rr = __fdividef(1.0f, m);
        float ir =  dr * rr;
        float ii = -di * rr;
        // four complex MACs sharing inv
        k00r += a.z * ir - a.w * ii;   k00i += a.z * ii + a.w * ir;
        k01r += b.x * ir - b.y * ii;   k01i += b.x * ii + b.y * ir;
        k10r += b.z * ir - b.w * ii;   k10i += b.z * ii + b.w * ir;
        k11r += cc.x * ir - cc.y * ii; k11i += cc.x * ii + cc.y * ir;
    }

    // atRoots = c * (k00 - k01 * k10 / (1 + k11))
    float tr = k01r * k10r - k01i * k10i;
    float ti = k01r * k10i + k01i * k10r;
    float er = 1.0f + k11r, ei = k11i;
    float rinv = __fdividef(1.0f, er * er + ei * ei);
    float sr = (tr * er + ti * ei) * rinv;
    float si = (ti * er - tr * ei) * rinv;
    float ar = k00r - sr, ai = k00i - si;

    // Output = Re(atRoots): complex64 reference cast to float32 keeps the
    // real part (out_size = L = 131071 float32 elements, odd).
    out[k] = c_r * ar - c_i * ai;
}

extern "C" void kernel_launch(void* const* d_in, const int* in_sizes, int n_in,
                              void* d_out, int out_size) {
    // Input ordering: dict order of setup_inputs() — confirmed by the R5
    // value-fingerprint classifier (Lambda_re all-negative at slot 0,
    // Lambda_im pi-scaled at slot 1, re-before-im).
    const float* Lr = (const float*)d_in[0];
    const float* Li = (const float*)d_in[1];
    const float* Pr = (const float*)d_in[2];
    const float* Pi = (const float*)d_in[3];
    const float* Qr = (const float*)d_in[4];
    const float* Qi = (const float*)d_in[5];
    const float* Br = (const float*)d_in[6];
    const float* Bi = (const float*)d_in[7];
    const float* Cr = (const float*)d_in[8];
    const float* Ci = (const float*)d_in[9];
    const float* step = (const float*)d_in[10];

    // out_size = L float32 elements (proven odd = 131071 = SEQ_L).
    int L = out_size;

    int threads = 256;
    int blocks = (L + threads - 1) / threads;
    s4_cauchy_kernel<<<blocks, threads>>>(Lr, Li, Pr, Pi, Qr, Qi, Br, Bi,
                                          Cr, Ci, step, (float*)d_out, L);
}

// round 8
// speedup vs baseline: 1.1404x; 1.1404x over previous
#include <cuda_runtime.h>

#define NSTATE 64

typedef unsigned long long u64;

__device__ __forceinline__ u64 add2(u64 a, u64 b) {
    u64 d; asm("add.rn.f32x2 %0,%1,%2;" : "=l"(d) : "l"(a), "l"(b)); return d;
}
__device__ __forceinline__ u64 mul2(u64 a, u64 b) {
    u64 d; asm("mul.rn.f32x2 %0,%1,%2;" : "=l"(d) : "l"(a), "l"(b)); return d;
}
__device__ __forceinline__ u64 ffma2(u64 a, u64 b, u64 c) {
    u64 d; asm("fma.rn.f32x2 %0,%1,%2,%3;" : "=l"(d) : "l"(a), "l"(b), "l"(c)); return d;
}
__device__ __forceinline__ u64 pk2(float x, float y) {
    u64 r; asm("mov.b64 %0,{%1,%2};" : "=l"(r) : "f"(x), "f"(y)); return r;
}
__device__ __forceinline__ void upk2(u64 a, float& x, float& y) {
    asm("mov.b64 {%0,%1},%2;" : "=f"(x), "=f"(y) : "l"(a));
}
__device__ __forceinline__ float rcpa(float x) {
    float r; asm("rcp.approx.f32 %0,%1;" : "=f"(r) : "f"(x)); return r;
}

// smem quantity indices
// 0:-Li  1:Lr^2  2:-Lr  3:v00r 4:v00i 5:v01r 6:v01i 7:v10r 8:v10i 9:v11r 10:v11i
// 11:-v00r 12:-v01r 13:-v10r 14:-v11r
__global__ __launch_bounds__(128) void s4_cauchy_kernel(
    const float* __restrict__ Lr, const float* __restrict__ Li,
    const float* __restrict__ Pr, const float* __restrict__ Pi,
    const float* __restrict__ Qr, const float* __restrict__ Qi,
    const float* __restrict__ Br, const float* __restrict__ Bi,
    const float* __restrict__ Cr, const float* __restrict__ Ci,
    const float* __restrict__ step_ptr,
    float* __restrict__ out, int L)
{
    __shared__ __align__(16) float sQ[15][NSTATE];
    __shared__ float sStep;

    const int t = threadIdx.x;
    if (t == 0) sStep = step_ptr[0];
    if (t < NSTATE) {
        float lr = Lr[t], li = Li[t];
        float cr = Cr[t], ci = Ci[t];
        float qr = Qr[t], qi = Qi[t];
        float br = Br[t], bi = Bi[t];
        float pr = Pr[t], pi = Pi[t];
        // v00 = conj(C)*B, v01 = conj(C)*P, v10 = conj(Q)*B, v11 = conj(Q)*P
        float v00r = cr * br + ci * bi, v00i = cr * bi - ci * br;
        float v01r = cr * pr + ci * pi, v01i = cr * pi - ci * pr;
        float v10r = qr * br + qi * bi, v10i = qr * bi - qi * br;
        float v11r = qr * pr + qi * pi, v11i = qr * pi - qi * pr;
        sQ[0][t]  = -li;
        sQ[1][t]  = lr * lr;
        sQ[2][t]  = -lr;
        sQ[3][t]  = v00r;  sQ[4][t]  = v00i;
        sQ[5][t]  = v01r;  sQ[6][t]  = v01i;
        sQ[7][t]  = v10r;  sQ[8][t]  = v10i;
        sQ[9][t]  = v11r;  sQ[10][t] = v11i;
        sQ[11][t] = -v00r; sQ[12][t] = -v01r;
        sQ[13][t] = -v10r; sQ[14][t] = -v11r;
    }
    __syncthreads();

    const int k = blockIdx.x * 128 + t;
    if (k >= L) return;

    // g = (2/step)*(1-Omega)/(1+Omega) is purely imaginary:
    //   gi = (2/step)*tan(pi*k/L),  and  c = 2/(1+Omega) = 1 + i*u,
    //   u = tan(pi*k/L).
    const float PI = 3.14159265358979323846f;
    float ang = PI * ((float)k / (float)L);
    float sn, cs;
    sincosf(ang, &sn, &cs);
    float u  = __fdividef(sn, cs);
    float gi = (2.0f / sStep) * u;
    const u64 gi2 = pk2(gi, gi);

    // packed accumulators (two states per lane-pair); 0ull == {0.f, 0.f}
    u64 a00r = 0, a00i = 0, a01r = 0, a01i = 0;
    u64 a10r = 0, a10i = 0, a11r = 0, a11i = 0;

#define BODY(H)                                                              \
    do {                                                                     \
        u64 di = add2(gi2, nli.H);          /* di = gi - Li           */     \
        u64 m  = ffma2(di, di, lr2.H);      /* m = Lr^2 + di^2        */     \
        float m0, m1; upk2(m, m0, m1);                                       \
        u64 rr = pk2(rcpa(m0), rcpa(m1));                                    \
        u64 ir = mul2(nlr.H, rr);           /* ir = dr/|d|^2, dr=-Lr  */     \
        u64 tt = mul2(di, rr);              /* tt = -ii = di/|d|^2    */     \
        a00r = ffma2(w00r.H, ir, a00r); a00r = ffma2(w00i.H, tt, a00r);      \
        a00i = ffma2(w00i.H, ir, a00i); a00i = ffma2(n00r.H, tt, a00i);      \
        a01r = ffma2(w01r.H, ir, a01r); a01r = ffma2(w01i.H, tt, a01r);      \
        a01i = ffma2(w01i.H, ir, a01i); a01i = ffma2(n01r.H, tt, a01i);      \
        a10r = ffma2(w10r.H, ir, a10r); a10r = ffma2(w10i.H, tt, a10r);      \
        a10i = ffma2(w10i.H, ir, a10i); a10i = ffma2(n10r.H, tt, a10i);      \
        a11r = ffma2(w11r.H, ir, a11r); a11r = ffma2(w11i.H, tt, a11r);      \
        a11i = ffma2(w11i.H, ir, a11i); a11i = ffma2(n11r.H, tt, a11i);      \
    } while (0)

#pragma unroll 2
    for (int p = 0; p < NSTATE / 4; p++) {
        ulonglong2 nli  = ((const ulonglong2*)sQ[0])[p];
        ulonglong2 lr2  = ((const ulonglong2*)sQ[1])[p];
        ulonglong2 nlr  = ((const ulonglong2*)sQ[2])[p];
        ulonglong2 w00r = ((const ulonglong2*)sQ[3])[p];
        ulonglong2 w00i = ((const ulonglong2*)sQ[4])[p];
        ulonglong2 w01r = ((const ulonglong2*)sQ[5])[p];
        ulonglong2 w01i = ((const ulonglong2*)sQ[6])[p];
        ulonglong2 w10r = ((const ulonglong2*)sQ[7])[p];
        ulonglong2 w10i = ((const ulonglong2*)sQ[8])[p];
        ulonglong2 w11r = ((const ulonglong2*)sQ[9])[p];
        ulonglong2 w11i = ((const ulonglong2*)sQ[10])[p];
        ulonglong2 n00r = ((const ulonglong2*)sQ[11])[p];
        ulonglong2 n01r = ((const ulonglong2*)sQ[12])[p];
        ulonglong2 n10r = ((const ulonglong2*)sQ[13])[p];
        ulonglong2 n11r = ((const ulonglong2*)sQ[14])[p];
        BODY(x);
        BODY(y);
    }
#undef BODY

    // reduce packed lanes
    float x0, x1;
    upk2(a00r, x0, x1); float k00r = x0 + x1;
    upk2(a00i, x0, x1); float k00i = x0 + x1;
    upk2(a01r, x0, x1); float k01r = x0 + x1;
    upk2(a01i, x0, x1); float k01i = x0 + x1;
    upk2(a10r, x0, x1); float k10r = x0 + x1;
    upk2(a10i, x0, x1); float k10i = x0 + x1;
    upk2(a11r, x0, x1); float k11r = x0 + x1;
    upk2(a11i, x0, x1); float k11i = x0 + x1;

    // atRoots = c * (k00 - k01*k10/(1+k11)),  c = 1 + i*u
    float tr = k01r * k10r - k01i * k10i;
    float ti = k01r * k10i + k01i * k10r;
    float er = 1.0f + k11r, ei = k11i;
    float rinv = __fdividef(1.0f, er * er + ei * ei);
    float sr = (tr * er + ti * ei) * rinv;
    float si = (ti * er - tr * ei) * rinv;
    float ar = k00r - sr, ai = k00i - si;

    // out = Re(atRoots) = ar - u*ai
    out[k] = ar - u * ai;
}

extern "C" void kernel_launch(void* const* d_in, const int* in_sizes, int n_in,
                              void* d_out, int out_size) {
    const float* Lr = (const float*)d_in[0];
    const float* Li = (const float*)d_in[1];
    const float* Pr = (const float*)d_in[2];
    const float* Pi = (const float*)d_in[3];
    const float* Qr = (const float*)d_in[4];
    const float* Qi = (const float*)d_in[5];
    const float* Br = (const float*)d_in[6];
    const float* Bi = (const float*)d_in[7];
    const float* Cr = (const float*)d_in[8];
    const float* Ci = (const float*)d_in[9];
    const float* step = (const float*)d_in[10];

    int L = out_size;  // L float32 elements = Re(atRoots)

    int threads = 128;
    int blocks = (L + threads - 1) / threads;
    s4_cauchy_kernel<<<blocks, threads>>>(Lr, Li, Pr, Pi, Qr, Qi, Br, Bi,
                                          Cr, Ci, step, (float*)d_out, L);
}